// round 10
// baseline (speedup 1.0000x reference)
#include <cuda_runtime.h>
#include <math.h>

// PatternBranch fused kernel for GB300 (sm_103a) — Round 6
// One block per sample (256 blocks x 256 threads).
// Thread t owns channels c0 = t&63 and c1 = c0+64.
// Conv dot products computed with packed fma.rn.f32x2 (even/odd term lanes),
// patch values loaded as ld.shared.b64 pairs (NHWC rows are contiguous).

#define NTHREADS 256
#define SMEM_ROW_F 196                 // 65 cols * 3 ch = 195, padded to 196
#define SMEM_FLOATS (65 * SMEM_ROW_F)  // 12740 floats = 50960 bytes
#define SMEM_BYTES (SMEM_FLOATS * 4)

__device__ __forceinline__ unsigned long long lds64(unsigned a) {
    unsigned long long v;
    asm volatile("ld.shared.b64 %0, [%1];" : "=l"(v) : "r"(a));
    return v;
}
__device__ __forceinline__ float lds32(unsigned a) {
    float v;
    asm volatile("ld.shared.f32 %0, [%1];" : "=f"(v) : "r"(a));
    return v;
}
__device__ __forceinline__ unsigned long long pk2(float x, float y) {
    unsigned long long r;
    asm("mov.b64 %0, {%1,%2};" : "=l"(r) : "f"(x), "f"(y));
    return r;
}
__device__ __forceinline__ void upk2(unsigned long long v, float& x, float& y) {
    asm("mov.b64 {%0,%1}, %2;" : "=f"(x), "=f"(y) : "l"(v));
}
__device__ __forceinline__ unsigned long long ffma2(
    unsigned long long a, unsigned long long b, unsigned long long c) {
    unsigned long long d;
    asm("fma.rn.f32x2 %0, %1, %2, %3;" : "=l"(d) : "l"(a), "l"(b), "l"(c));
    return d;
}

__global__ void __launch_bounds__(NTHREADS, 2) pattern_branch_kernel(
    const float* __restrict__ g_in,     // [256,64,64,3]
    const float* __restrict__ conv_w,   // [3,3,3,128]
    const float* __restrict__ conv_b,   // [128]
    const float* __restrict__ match_w,  // [128]
    const float* __restrict__ match_b,  // [1]
    const float* __restrict__ pat_w,    // [32*32*32]
    const float* __restrict__ pat_b,    // [1]
    const float* __restrict__ base_w,   // [32*32*128, 3]
    const float* __restrict__ base_b,   // [3]
    const int*   __restrict__ psi,      // [32]
    float* __restrict__ out)            // [256,3]
{
    extern __shared__ float in_s[];
    __shared__ float red[8][5];

    const int tid = threadIdx.x;
    const int b   = blockIdx.x;

    // ---- Stage input sample into smem, zero-padding row 64 and col 64 ----
    float4* s4 = reinterpret_cast<float4*>(in_s);
    for (int i = tid; i < 65 + 48; i += NTHREADS) {
        if (i < 65) s4[i * 49 + 48] = make_float4(0.f, 0.f, 0.f, 0.f);
        else        s4[64 * 49 + (i - 65)] = make_float4(0.f, 0.f, 0.f, 0.f);
    }
    const float4* g4 = reinterpret_cast<const float4*>(g_in + (size_t)b * 12288);
    for (int i = tid; i < 64 * 48; i += NTHREADS) {
        int r = i / 48;
        int q = i - r * 48;
        s4[r * 49 + q] = g4[r * 48 + q];
    }

    // ---- Per-thread setup (overlaps other warps' fill) ----
    const int c0  = tid & 63;
    const int c1  = c0 + 64;
    const int grp = tid >> 6;

    // Packed conv weights: per kernel-row (9 terms) -> 4 pairs + 1 single.
    // Pair p of row kh pairs terms (kh*9+2p, kh*9+2p+1).
    unsigned long long wp0[12], wp1[12];
    float ws0[3], ws1[3];
#pragma unroll
    for (int kh = 0; kh < 3; ++kh) {
#pragma unroll
        for (int p = 0; p < 4; ++p) {
            int j = kh * 9 + 2 * p;
            wp0[kh * 4 + p] = pk2(conv_w[j * 128 + c0], conv_w[(j + 1) * 128 + c0]);
            wp1[kh * 4 + p] = pk2(conv_w[j * 128 + c1], conv_w[(j + 1) * 128 + c1]);
        }
        ws0[kh] = conv_w[(kh * 9 + 8) * 128 + c0];
        ws1[kh] = conv_w[(kh * 9 + 8) * 128 + c1];
    }
    const unsigned long long cbp0 = pk2(conv_b[c0], 0.f);
    const unsigned long long cbp1 = pk2(conv_b[c1], 0.f);

    // pattern gather bitmasks
    unsigned m0 = 0, m1 = 0;
#pragma unroll
    for (int k = 0; k < 32; ++k) {
        int ic = psi[k];
        if (ic == c0) m0 |= 1u << k;
        if (ic == c1) m1 |= 1u << k;
    }

    const unsigned sbase = (unsigned)__cvta_generic_to_shared(in_s);

    __syncthreads();

    // ---- Main fused loop: 256 positions, 2 channels each ----
    float fsum0 = 0.f, fsum1 = 0.f;
    float pacc  = 0.f;
    float ba0 = 0.f, ba1 = 0.f, ba2 = 0.f;

    const int posBase = grp * 256;
    for (int i = 0; i < 256; ++i) {
        const int pos = posBase + i;
        const int oh = pos >> 5;
        const int ow = pos & 31;

        // Issue L2-latency base_w loads first so conv math hides them.
        const float* bw = base_w + ((pos * 128 + c0) * 3);
        const float b00 = bw[0],   b01 = bw[1],   b02 = bw[2];
        const float b10 = bw[192], b11 = bw[193], b12 = bw[194];

        // Patch values: 3 rows x 9 contiguous floats, loaded as 4x b64 + 1x f32.
        const unsigned pb = sbase + (unsigned)(((oh * 2) * SMEM_ROW_F + ow * 6) * 4);
        unsigned long long v[12];
        float vs[3];
#pragma unroll
        for (int kh = 0; kh < 3; ++kh) {
            const unsigned ra = pb + (unsigned)(kh * (SMEM_ROW_F * 4));
            v[kh * 4 + 0] = lds64(ra);
            v[kh * 4 + 1] = lds64(ra + 8);
            v[kh * 4 + 2] = lds64(ra + 16);
            v[kh * 4 + 3] = lds64(ra + 24);
            vs[kh] = lds32(ra + 32);
        }

        // Channel c0: packed dot (lane0 = even terms, lane1 = odd terms)
        unsigned long long a0 = ffma2(v[0], wp0[0], cbp0);
#pragma unroll
        for (int t = 1; t < 12; ++t) a0 = ffma2(v[t], wp0[t], a0);
        float s0 = vs[0] * ws0[0];
        s0 = fmaf(vs[1], ws0[1], s0);
        s0 = fmaf(vs[2], ws0[2], s0);

        // Channel c1
        unsigned long long a1 = ffma2(v[0], wp1[0], cbp1);
#pragma unroll
        for (int t = 1; t < 12; ++t) a1 = ffma2(v[t], wp1[t], a1);
        float s1 = vs[0] * ws1[0];
        s1 = fmaf(vs[1], ws1[1], s1);
        s1 = fmaf(vs[2], ws1[2], s1);

        float lo0, hi0, lo1, hi1;
        upk2(a0, lo0, hi0);
        upk2(a1, lo1, hi1);
        const float f0 = fmaxf(lo0 + hi0 + s0, 0.f);
        const float f1 = fmaxf(lo1 + hi1 + s1, 0.f);

        fsum0 += f0;
        fsum1 += f1;

        ba0 = fmaf(f0, b00, ba0);
        ba1 = fmaf(f0, b01, ba1);
        ba2 = fmaf(f0, b02, ba2);
        ba0 = fmaf(f1, b10, ba0);
        ba1 = fmaf(f1, b11, ba1);
        ba2 = fmaf(f1, b12, ba2);

        if (m0) {
            unsigned mm = m0;
            do {
                int k = __ffs(mm) - 1;
                pacc = fmaf(f0, pat_w[pos * 32 + k], pacc);
                mm &= mm - 1;
            } while (mm);
        }
        if (m1) {
            unsigned mm = m1;
            do {
                int k = __ffs(mm) - 1;
                pacc = fmaf(f1, pat_w[pos * 32 + k], pacc);
                mm &= mm - 1;
            } while (mm);
        }
    }

    // ---- Block reduction of 5 scalars (deterministic tree) ----
    float v0 = fsum0 * match_w[c0] + fsum1 * match_w[c1];
    float v1 = pacc, v2 = ba0, v3 = ba1, v4 = ba2;
#pragma unroll
    for (int off = 16; off > 0; off >>= 1) {
        v0 += __shfl_down_sync(0xffffffffu, v0, off);
        v1 += __shfl_down_sync(0xffffffffu, v1, off);
        v2 += __shfl_down_sync(0xffffffffu, v2, off);
        v3 += __shfl_down_sync(0xffffffffu, v3, off);
        v4 += __shfl_down_sync(0xffffffffu, v4, off);
    }
    const int warp = tid >> 5;
    const int lane = tid & 31;
    if (lane == 0) {
        red[warp][0] = v0; red[warp][1] = v1; red[warp][2] = v2;
        red[warp][3] = v3; red[warp][4] = v4;
    }
    __syncthreads();

    if (tid == 0) {
        float s0 = 0.f, s1 = 0.f, s2 = 0.f, s3 = 0.f, s4v = 0.f;
#pragma unroll
        for (int w = 0; w < 8; ++w) {
            s0 += red[w][0]; s1 += red[w][1]; s2 += red[w][2];
            s3 += red[w][3]; s4v += red[w][4];
        }
        const float matchv = s0 * (1.0f / 1024.0f) + match_b[0];
        const float plog = s1 + pat_b[0];
        const float pp = 1.0f / (1.0f + expf(-plog));
        const float l0 = s2 + base_b[0];
        const float l1 = s3 + base_b[1];
        const float l2 = s4v + base_b[2];
        const float mx = fmaxf(l0, fmaxf(l1, l2));
        const float e0 = expf(l0 - mx);
        const float e1 = expf(l1 - mx);
        const float e2 = expf(l2 - mx);
        const float inv = 1.0f / (e0 + e1 + e2);

        float o0, o1, o2;
        if (matchv > 0.0f && plog >= 0.0f) {
            o0 = pp;
            o1 = 0.5f * (1.0f - pp);
            o2 = o1;
        } else {
            o0 = e0 * inv;
            o1 = e1 * inv;
            o2 = e2 * inv;
        }
        out[b * 3 + 0] = o0;
        out[b * 3 + 1] = o1;
        out[b * 3 + 2] = o2;
    }
}

extern "C" void kernel_launch(void* const* d_in, const int* in_sizes, int n_in,
                              void* d_out, int out_size)
{
    (void)in_sizes; (void)n_in; (void)out_size;
    const float* g_in    = (const float*)d_in[0];
    const float* conv_w  = (const float*)d_in[1];
    const float* conv_b  = (const float*)d_in[2];
    const float* match_w = (const float*)d_in[3];
    const float* match_b = (const float*)d_in[4];
    const float* pat_w   = (const float*)d_in[5];
    const float* pat_b   = (const float*)d_in[6];
    const float* base_w  = (const float*)d_in[7];
    const float* base_b  = (const float*)d_in[8];
    const int*   psi     = (const int*)d_in[9];
    float* out = (float*)d_out;

    cudaFuncSetAttribute(pattern_branch_kernel,
                         cudaFuncAttributeMaxDynamicSharedMemorySize, SMEM_BYTES);

    pattern_branch_kernel<<<256, NTHREADS, SMEM_BYTES>>>(
        g_in, conv_w, conv_b, match_w, match_b,
        pat_w, pat_b, base_w, base_b, psi, out);
}

// round 11
// speedup vs baseline: 2.0428x; 2.0428x over previous
#include <cuda_runtime.h>
#include <math.h>

// PatternBranch fused kernel — Round 10
// Prologue folds base_w + gathered pat_w into a float4 table (1 LDG.128/(pos,ch)).
// Main: 256 blocks x 256 thr; thread owns channels c0=tid&63, c1=c0+64;
// position pairs (even/odd ow) share one 16-float smem row load and one weight set.

#define NTHREADS 256
#define SMEM_ROW_F 196                 // 65 cols * 3 ch = 195, padded to 196
#define SMEM_FLOATS (65 * SMEM_ROW_F)
#define SMEM_BYTES (SMEM_FLOATS * 4)

__device__ float4 g_bw4[1024 * 128];   // (b0, b1, b2, folded pat weight) — 2 MB scratch

__device__ __forceinline__ unsigned long long lds64(unsigned a) {
    unsigned long long v;
    asm volatile("ld.shared.b64 %0, [%1];" : "=l"(v) : "r"(a));
    return v;
}
__device__ __forceinline__ unsigned long long pk2(float x, float y) {
    unsigned long long r;
    asm("mov.b64 %0, {%1,%2};" : "=l"(r) : "f"(x), "f"(y));
    return r;
}
__device__ __forceinline__ void upk2(unsigned long long v, float& x, float& y) {
    asm("mov.b64 {%0,%1}, %2;" : "=f"(x), "=f"(y) : "l"(v));
}
__device__ __forceinline__ unsigned long long ffma2(
    unsigned long long a, unsigned long long b, unsigned long long c) {
    unsigned long long d;
    asm("fma.rn.f32x2 %0, %1, %2, %3;" : "=l"(d) : "l"(a), "l"(b), "l"(c));
    return d;
}

// ---- Prologue: build fused (base_w, pat) float4 table ----
__global__ void __launch_bounds__(256) prep_kernel(
    const float* __restrict__ base_w,   // [1024*128, 3]
    const float* __restrict__ pat_w,    // [1024*32]
    const int*   __restrict__ psi)      // [32]
{
    const int idx = blockIdx.x * blockDim.x + threadIdx.x;  // 131072
    const int pos = idx >> 7;
    const int c   = idx & 127;
    const float b0 = base_w[idx * 3 + 0];
    const float b1 = base_w[idx * 3 + 1];
    const float b2 = base_w[idx * 3 + 2];
    float pw = 0.f;
#pragma unroll
    for (int k = 0; k < 32; ++k)
        if (psi[k] == c) pw += pat_w[pos * 32 + k];
    g_bw4[idx] = make_float4(b0, b1, b2, pw);
}

// ---- Main fused kernel ----
__global__ void __launch_bounds__(NTHREADS, 2) pattern_branch_kernel(
    const float* __restrict__ g_in,     // [256,64,64,3]
    const float* __restrict__ conv_w,   // [3,3,3,128]
    const float* __restrict__ conv_b,   // [128]
    const float* __restrict__ match_w,  // [128]
    const float* __restrict__ match_b,  // [1]
    const float* __restrict__ pat_b,    // [1]
    const float* __restrict__ base_b,   // [3]
    float* __restrict__ out)            // [256,3]
{
    extern __shared__ float in_s[];
    __shared__ float red[8][5];

    const int tid = threadIdx.x;
    const int b   = blockIdx.x;

    // ---- Stage input sample into smem, zero-padding row 64 and col 64 ----
    float4* s4 = reinterpret_cast<float4*>(in_s);
    for (int i = tid; i < 65 + 48; i += NTHREADS) {
        if (i < 65) s4[i * 49 + 48] = make_float4(0.f, 0.f, 0.f, 0.f);
        else        s4[64 * 49 + (i - 65)] = make_float4(0.f, 0.f, 0.f, 0.f);
    }
    const float4* g4 = reinterpret_cast<const float4*>(g_in + (size_t)b * 12288);
    for (int i = tid; i < 64 * 48; i += NTHREADS) {
        int r = i / 48;
        int q = i - r * 48;
        s4[r * 49 + q] = g4[r * 48 + q];
    }

    // ---- Per-thread setup ----
    const int c0  = tid & 63;
    const int c1  = c0 + 64;
    const int grp = tid >> 6;

    // Packed conv weights: per row kh, 5 pairs: (w0,w1)(w2,w3)(w4,w5)(w6,w7)(w8,0).
    // Pair alignment works for BOTH positions of a pair (B's terms sit at float
    // offset +6, still even-aligned; pair 4's second lane multiplies garbage by 0).
    unsigned long long wp0[15], wp1[15];
#pragma unroll
    for (int kh = 0; kh < 3; ++kh) {
#pragma unroll
        for (int p = 0; p < 4; ++p) {
            int j = kh * 9 + 2 * p;
            wp0[kh * 5 + p] = pk2(conv_w[j * 128 + c0], conv_w[(j + 1) * 128 + c0]);
            wp1[kh * 5 + p] = pk2(conv_w[j * 128 + c1], conv_w[(j + 1) * 128 + c1]);
        }
        wp0[kh * 5 + 4] = pk2(conv_w[(kh * 9 + 8) * 128 + c0], 0.f);
        wp1[kh * 5 + 4] = pk2(conv_w[(kh * 9 + 8) * 128 + c1], 0.f);
    }
    const float cb0 = conv_b[c0];
    const float cb1 = conv_b[c1];

    const unsigned sbase = (unsigned)__cvta_generic_to_shared(in_s);
    const float4* __restrict__ bw4 = g_bw4;

    __syncthreads();

    // ---- Main loop: 128 position-pairs (posA even, posB = posA+1) ----
    float fsum0 = 0.f, fsum1 = 0.f;
    float pacc  = 0.f;
    float ba0 = 0.f, ba1 = 0.f, ba2 = 0.f;

    const int posBase = grp * 256;
    for (int i2 = 0; i2 < 128; ++i2) {
        const int posA = posBase + 2 * i2;
        const int oh = posA >> 5;
        const int owA = posA & 31;          // even

        // One LDG.128 per (pos, ch): base weights + folded pattern weight.
        // Issued first; consumed after the full conv body (latency hidden).
        const float4 bA0 = __ldg(&bw4[posA * 128 + c0]);
        const float4 bA1 = __ldg(&bw4[posA * 128 + c1]);
        const float4 bB0 = __ldg(&bw4[posA * 128 + 128 + c0]);
        const float4 bB1 = __ldg(&bw4[posA * 128 + 128 + c1]);

        // Conv: 4 independent FFMA2 chains (2 pos x 2 ch), shared row loads.
        unsigned long long aA0 = 0ull, aA1 = 0ull, aB0 = 0ull, aB1 = 0ull;
#pragma unroll
        for (int kh = 0; kh < 3; ++kh) {
            const unsigned ra = sbase
                + (unsigned)((((oh * 2 + kh) * SMEM_ROW_F) + owA * 6) * 4);
            unsigned long long v0 = lds64(ra);
            unsigned long long v1 = lds64(ra + 8);
            unsigned long long v2 = lds64(ra + 16);
            unsigned long long v3 = lds64(ra + 24);
            unsigned long long v4 = lds64(ra + 32);
            unsigned long long v5 = lds64(ra + 40);
            unsigned long long v6 = lds64(ra + 48);
            unsigned long long v7 = lds64(ra + 56);
            // pos A uses floats 0..9 -> pairs v0..v4
            aA0 = ffma2(v0, wp0[kh * 5 + 0], aA0);
            aA1 = ffma2(v0, wp1[kh * 5 + 0], aA1);
            aA0 = ffma2(v1, wp0[kh * 5 + 1], aA0);
            aA1 = ffma2(v1, wp1[kh * 5 + 1], aA1);
            aA0 = ffma2(v2, wp0[kh * 5 + 2], aA0);
            aA1 = ffma2(v2, wp1[kh * 5 + 2], aA1);
            aA0 = ffma2(v3, wp0[kh * 5 + 3], aA0);
            aA1 = ffma2(v3, wp1[kh * 5 + 3], aA1);
            aA0 = ffma2(v4, wp0[kh * 5 + 4], aA0);
            aA1 = ffma2(v4, wp1[kh * 5 + 4], aA1);
            // pos B uses floats 6..15 -> pairs v3..v7 (same weights)
            aB0 = ffma2(v3, wp0[kh * 5 + 0], aB0);
            aB1 = ffma2(v3, wp1[kh * 5 + 0], aB1);
            aB0 = ffma2(v4, wp0[kh * 5 + 1], aB0);
            aB1 = ffma2(v4, wp1[kh * 5 + 1], aB1);
            aB0 = ffma2(v5, wp0[kh * 5 + 2], aB0);
            aB1 = ffma2(v5, wp1[kh * 5 + 2], aB1);
            aB0 = ffma2(v6, wp0[kh * 5 + 3], aB0);
            aB1 = ffma2(v6, wp1[kh * 5 + 3], aB1);
            aB0 = ffma2(v7, wp0[kh * 5 + 4], aB0);
            aB1 = ffma2(v7, wp1[kh * 5 + 4], aB1);
        }

        float lA0, hA0, lA1, hA1, lB0, hB0, lB1, hB1;
        upk2(aA0, lA0, hA0);
        upk2(aA1, lA1, hA1);
        upk2(aB0, lB0, hB0);
        upk2(aB1, lB1, hB1);
        const float fA0 = fmaxf(lA0 + hA0 + cb0, 0.f);
        const float fA1 = fmaxf(lA1 + hA1 + cb1, 0.f);
        const float fB0 = fmaxf(lB0 + hB0 + cb0, 0.f);
        const float fB1 = fmaxf(lB1 + hB1 + cb1, 0.f);

        fsum0 += fA0 + fB0;
        fsum1 += fA1 + fB1;

        ba0 = fmaf(fA0, bA0.x, ba0);  ba1 = fmaf(fA0, bA0.y, ba1);
        ba2 = fmaf(fA0, bA0.z, ba2);  pacc = fmaf(fA0, bA0.w, pacc);
        ba0 = fmaf(fA1, bA1.x, ba0);  ba1 = fmaf(fA1, bA1.y, ba1);
        ba2 = fmaf(fA1, bA1.z, ba2);  pacc = fmaf(fA1, bA1.w, pacc);
        ba0 = fmaf(fB0, bB0.x, ba0);  ba1 = fmaf(fB0, bB0.y, ba1);
        ba2 = fmaf(fB0, bB0.z, ba2);  pacc = fmaf(fB0, bB0.w, pacc);
        ba0 = fmaf(fB1, bB1.x, ba0);  ba1 = fmaf(fB1, bB1.y, ba1);
        ba2 = fmaf(fB1, bB1.z, ba2);  pacc = fmaf(fB1, bB1.w, pacc);
    }

    // ---- Block reduction of 5 scalars (deterministic tree) ----
    float v0 = fsum0 * match_w[c0] + fsum1 * match_w[c1];
    float v1 = pacc, v2 = ba0, v3 = ba1, v4 = ba2;
#pragma unroll
    for (int off = 16; off > 0; off >>= 1) {
        v0 += __shfl_down_sync(0xffffffffu, v0, off);
        v1 += __shfl_down_sync(0xffffffffu, v1, off);
        v2 += __shfl_down_sync(0xffffffffu, v2, off);
        v3 += __shfl_down_sync(0xffffffffu, v3, off);
        v4 += __shfl_down_sync(0xffffffffu, v4, off);
    }
    const int warp = tid >> 5;
    const int lane = tid & 31;
    if (lane == 0) {
        red[warp][0] = v0; red[warp][1] = v1; red[warp][2] = v2;
        red[warp][3] = v3; red[warp][4] = v4;
    }
    __syncthreads();

    if (tid == 0) {
        float s0 = 0.f, s1 = 0.f, s2 = 0.f, s3 = 0.f, s4v = 0.f;
#pragma unroll
        for (int w = 0; w < 8; ++w) {
            s0 += red[w][0]; s1 += red[w][1]; s2 += red[w][2];
            s3 += red[w][3]; s4v += red[w][4];
        }
        const float matchv = s0 * (1.0f / 1024.0f) + match_b[0];
        const float plog = s1 + pat_b[0];
        const float pp = 1.0f / (1.0f + expf(-plog));
        const float l0 = s2 + base_b[0];
        const float l1 = s3 + base_b[1];
        const float l2 = s4v + base_b[2];
        const float mx = fmaxf(l0, fmaxf(l1, l2));
        const float e0 = expf(l0 - mx);
        const float e1 = expf(l1 - mx);
        const float e2 = expf(l2 - mx);
        const float inv = 1.0f / (e0 + e1 + e2);

        float o0, o1, o2;
        if (matchv > 0.0f && plog >= 0.0f) {
            o0 = pp;
            o1 = 0.5f * (1.0f - pp);
            o2 = o1;
        } else {
            o0 = e0 * inv;
            o1 = e1 * inv;
            o2 = e2 * inv;
        }
        out[b * 3 + 0] = o0;
        out[b * 3 + 1] = o1;
        out[b * 3 + 2] = o2;
    }
}

extern "C" void kernel_launch(void* const* d_in, const int* in_sizes, int n_in,
                              void* d_out, int out_size)
{
    (void)in_sizes; (void)n_in; (void)out_size;
    const float* g_in    = (const float*)d_in[0];
    const float* conv_w  = (const float*)d_in[1];
    const float* conv_b  = (const float*)d_in[2];
    const float* match_w = (const float*)d_in[3];
    const float* match_b = (const float*)d_in[4];
    const float* pat_w   = (const float*)d_in[5];
    const float* pat_b   = (const float*)d_in[6];
    const float* base_w  = (const float*)d_in[7];
    const float* base_b  = (const float*)d_in[8];
    const int*   psi     = (const int*)d_in[9];
    float* out = (float*)d_out;

    cudaFuncSetAttribute(pattern_branch_kernel,
                         cudaFuncAttributeMaxDynamicSharedMemorySize, SMEM_BYTES);

    // Prologue: fold base_w + gathered pat_w into float4 table (same stream,
    // ordered before the main kernel; both graph-capturable).
    prep_kernel<<<512, 256>>>(base_w, pat_w, psi);

    pattern_branch_kernel<<<256, NTHREADS, SMEM_BYTES>>>(
        g_in, conv_w, conv_b, match_w, match_b,
        pat_b, base_b, out);
}